// round 17
// baseline (speedup 1.0000x reference)
#include <cuda_runtime.h>
#include <cuda_fp16.h>
#include <cstdint>

#define N_NODES 50000
#define N_EDGES 1600000
#define D_FEAT  64
#define D_OUT   128
#define K_DIM   192
#define BM      64

#define LDA    72            // fp16 leading dim of A rows (144 B)
#define CHS    4608          // A chunk stride: 32 rows * 144 B
#define GBUF   16896         // per-group buffer: max(A 13824, stage 32*132*4)
#define GPART  33792         // per-group partition: 2 buffers
#define SMEM_DYN 67584
#define LDST   132           // fp32 stage leading dim (floats)

// Weights pre-packed in mma-fragment PAIR order: [12 ksteps][8 ngroup-pairs][32 lanes] uint4
__device__ __align__(16) uint4 g_We_f[12 * 8 * 32];
__device__ __align__(16) uint4 g_Wn_f[12 * 8 * 32];
__device__ float g_received[(size_t)N_NODES * D_OUT];

// ---------------------------------------------------------------------------
static __device__ __forceinline__ uint32_t smem_u32(const void* p) {
    uint32_t a;
    asm("{ .reg .u64 t; cvta.to.shared.u64 t, %1; cvt.u32.u64 %0, t; }" : "=r"(a) : "l"(p));
    return a;
}
static __device__ __forceinline__ void ldm4(uint32_t* r, uint32_t addr) {
    asm volatile("ldmatrix.sync.aligned.m8n8.x4.shared.b16 {%0,%1,%2,%3}, [%4];"
                 : "=r"(r[0]), "=r"(r[1]), "=r"(r[2]), "=r"(r[3]) : "r"(addr));
}
static __device__ __forceinline__ void mma16816(float* c, const uint32_t* a, const uint32_t* b) {
    asm volatile(
        "mma.sync.aligned.m16n8k16.row.col.f32.f16.f16.f32 "
        "{%0,%1,%2,%3}, {%4,%5,%6,%7}, {%8,%9}, {%0,%1,%2,%3};"
        : "+f"(c[0]), "+f"(c[1]), "+f"(c[2]), "+f"(c[3])
        : "r"(a[0]), "r"(a[1]), "r"(a[2]), "r"(a[3]), "r"(b[0]), "r"(b[1]));
}
static __device__ __forceinline__ void hbar(int wg) {
    asm volatile("bar.sync %0, 128;" :: "r"(wg + 1) : "memory");
}

// ---------------------------------------------------------------------------
__global__ void prep_w_kernel(const float* __restrict__ We, const float* __restrict__ Wn) {
    int idx = blockIdx.x * blockDim.x + threadIdx.x;
    if (idx >= 2 * 12 * 8 * 32) return;
    int m    = idx / (12 * 8 * 32);
    int rest = idx % (12 * 8 * 32);
    int l    = rest & 31;
    int pid  = rest >> 5;
    int s    = pid >> 3;
    int p    = pid & 7;
    const float* W = m ? Wn : We;
    int k0 = s * 16 + (l & 3) * 2;
    uint4 out;
    #pragma unroll
    for (int h = 0; h < 2; h++) {
        int n = (2 * p + h) * 8 + (l >> 2);
        __half2 b0 = __floats2half2_rn(W[(size_t)k0 * D_OUT + n],       W[(size_t)(k0 + 1) * D_OUT + n]);
        __half2 b1 = __floats2half2_rn(W[(size_t)(k0 + 8) * D_OUT + n], W[(size_t)(k0 + 9) * D_OUT + n]);
        if (h == 0) { out.x = *(uint32_t*)&b0; out.y = *(uint32_t*)&b1; }
        else        { out.z = *(uint32_t*)&b0; out.w = *(uint32_t*)&b1; }
    }
    (m ? g_Wn_f : g_We_f)[rest] = out;
}

__global__ void zero_received_kernel() {
    size_t n4 = (size_t)N_NODES * D_OUT / 4;
    float4* p = reinterpret_cast<float4*>(g_received);
    for (size_t i = blockIdx.x * blockDim.x + threadIdx.x; i < n4;
         i += (size_t)gridDim.x * blockDim.x)
        p[i] = make_float4(0.f, 0.f, 0.f, 0.f);
}

// ---------------------------------------------------------------------------
// Persistent fused GEMM: BM=64 tiles; two independent 128-thread pipelines
// with byte-disjoint smem partitions. Warp-per-row gather (contiguous LDG.64
// + STS.32), mma with B frags from L1, staged epilogue drained warp-per-row
// (contiguous LDS.128 -> STG.128 + red.v4). Fused scatter-add (EDGE).
// ---------------------------------------------------------------------------
template <bool EDGE>
__global__ __launch_bounds__(256, 3)
void gnn_kernel(const float* __restrict__ nodes,
                const float* __restrict__ edges,
                const int*   __restrict__ senders,
                const int*   __restrict__ receivers,
                const float* __restrict__ bias,
                float* __restrict__ outbuf,
                int t0, int ntiles)
{
    extern __shared__ __align__(16) char sp[];
    const uint32_t smbase = smem_u32(sp);

    __shared__ int s_snd[2][2][32];   // [group][buf][row]
    __shared__ int s_rcv[2][2][32];

    const int tid  = threadIdx.x;
    const int wid  = tid >> 5;
    const int lid  = tid & 31;
    const int wg   = wid >> 2;            // half-CTA group (0 or 1)
    const int wid4 = wid & 3;             // warp within group
    const int wn   = wid4 * 32;           // warp n-origin
    const int pb   = wid4 * 2;            // B ngroup-pair base
    const int gl   = tid & 127;           // group-local tid

    const uint4* __restrict__ Wf = EDGE ? g_We_f : g_Wn_f;

    const int a_row = (lid & 7) + ((lid >> 3) & 1) * 8;
    const int a_kof = (lid >> 4) * 8;

    // per-lane bias (128 cols covered by 32 lanes x float4)
    const float4 bb4 = *(const float4*)&bias[lid * 4];

    const uint32_t part = smbase + wg * GPART;

    const int stride = gridDim.x;
    const int tend   = t0 + ntiles;
    int t = t0 + blockIdx.x;

    // warp-per-row gather: chunk c of tile tt into this group's buffer `buf`
    auto do_gather = [&](int c, int tt, int buf) {
        #pragma unroll
        for (int it = 0; it < 8; it++) {
            const int r = it * 4 + wid4;          // local row 0..31
            const float* src;
            if (EDGE) {
                if (c == 0)      src = edges + (size_t)(tt * BM + wg * 32 + r) * D_FEAT;
                else if (c == 1) src = nodes + (size_t)s_snd[wg][buf][r] * D_FEAT;
                else             src = nodes + (size_t)s_rcv[wg][buf][r] * D_FEAT;
            } else {
                int rg = tt * BM + wg * 32 + r;
                if (rg >= N_NODES) rg = N_NODES - 1;
                if (c == 0)      src = nodes + (size_t)rg * D_FEAT;
                else             src = g_received + (size_t)rg * D_OUT + (c - 1) * 64;
            }
            float2 v = ((const float2*)src)[lid];
            __half2 h = __floats2half2_rn(v.x, v.y);
            *(__half2*)(sp + wg * GPART + buf * GBUF + c * CHS + r * 144 + lid * 4) = h;
        }
    };

    // ---- prologue: indices + gather first tile into buffer 0 ----
    if (EDGE && gl < 32) {
        s_snd[wg][0][gl] = senders[t * BM + wg * 32 + gl];
        s_rcv[wg][0][gl] = receivers[t * BM + wg * 32 + gl];
    }
    hbar(wg);
    #pragma unroll
    for (int c = 0; c < 3; c++) do_gather(c, t, 0);

    int cur = 0;
    for (; t < tend; t += stride) {
        const int tn = t + stride;
        const bool hn = tn < tend;
        if (EDGE && hn && gl < 32) {
            s_snd[wg][cur ^ 1][gl] = senders[tn * BM + wg * 32 + gl];
            s_rcv[wg][cur ^ 1][gl] = receivers[tn * BM + wg * 32 + gl];
        }
        hbar(wg);                          // A[cur] + next indices visible

        const uint32_t sA = part + cur * GBUF;

        float acc[2][4][4];
        #pragma unroll
        for (int mt = 0; mt < 2; mt++)
            #pragma unroll
            for (int nt = 0; nt < 4; nt++)
                #pragma unroll
                for (int i = 0; i < 4; i++) acc[mt][nt][i] = 0.f;

        #pragma unroll
        for (int c = 0; c < 3; c++) {
            #pragma unroll
            for (int ksl = 0; ksl < 4; ksl++) {
                const int ks = c * 4 + ksl;
                uint32_t ah[2][4];
                uint4 bq[2];
                ldm4(ah[0], sA + c * CHS + ((     a_row) * LDA + ksl * 16 + a_kof) * 2);
                ldm4(ah[1], sA + c * CHS + ((16 + a_row) * LDA + ksl * 16 + a_kof) * 2);
                bq[0] = __ldg(&Wf[(ks * 8 + pb)     * 32 + lid]);
                bq[1] = __ldg(&Wf[(ks * 8 + pb + 1) * 32 + lid]);
                #pragma unroll
                for (int mt = 0; mt < 2; mt++) {
                    mma16816(acc[mt][0], ah[mt], (const uint32_t*)&bq[0].x);
                    mma16816(acc[mt][1], ah[mt], (const uint32_t*)&bq[0].z);
                    mma16816(acc[mt][2], ah[mt], (const uint32_t*)&bq[1].x);
                    mma16816(acc[mt][3], ah[mt], (const uint32_t*)&bq[1].z);
                }
            }
            // overlap: gather chunk c of next tile into this group's A[cur^1]
            if (hn) do_gather(c, tn, cur ^ 1);
        }
        hbar(wg);                          // mma reads of A[cur] done

        // ---- stage: fragments -> fp32 stage in retired A[cur] buffer ----
        float* stage = (float*)(sp + wg * GPART + cur * GBUF);   // [32][132]
        {
            const int cr = lid >> 2;
            const int cc = (lid & 3) * 2;
            #pragma unroll
            for (int mt = 0; mt < 2; mt++)
                #pragma unroll
                for (int nt = 0; nt < 4; nt++) {
                    int r  = mt * 16 + cr;
                    int cx = wn + nt * 8 + cc;
                    *(float2*)&stage[r * LDST + cx]       = make_float2(acc[mt][nt][0], acc[mt][nt][1]);
                    *(float2*)&stage[(r + 8) * LDST + cx] = make_float2(acc[mt][nt][2], acc[mt][nt][3]);
                }
        }
        hbar(wg);                          // stage complete

        // ---- drain: warp-per-row, fully contiguous ----
        {
            #pragma unroll
            for (int it = 0; it < 8; it++) {
                const int r   = it * 4 + wid4;
                const int row = t * BM + wg * 32 + r;
                const bool live = EDGE || row < N_NODES;
                float4 s = *(const float4*)&stage[r * LDST + lid * 4];
                float4 v;
                v.x = fmaxf(s.x + bb4.x, 0.f);
                v.y = fmaxf(s.y + bb4.y, 0.f);
                v.z = fmaxf(s.z + bb4.z, 0.f);
                v.w = fmaxf(s.w + bb4.w, 0.f);
                if (live) {
                    *(float4*)&outbuf[(size_t)row * D_OUT + lid * 4] = v;
                    if (EDGE) {
                        float* rp = g_received + (size_t)s_rcv[wg][cur][r] * D_OUT + lid * 4;
                        asm volatile("red.global.add.v4.f32 [%0], {%1,%2,%3,%4};"
                                     :: "l"(rp), "f"(v.x), "f"(v.y), "f"(v.z), "f"(v.w) : "memory");
                    }
                }
            }
        }
        cur ^= 1;
    }
}

// ---------------------------------------------------------------------------
extern "C" void kernel_launch(void* const* d_in, const int* in_sizes, int n_in,
                              void* d_out, int out_size)
{
    const float* nodes     = (const float*)d_in[0];
    const float* edges     = (const float*)d_in[1];
    const int*   senders   = (const int*)d_in[2];
    const int*   receivers = (const int*)d_in[3];
    const float* W_edge    = (const float*)d_in[4];
    const float* b_edge    = (const float*)d_in[5];
    const float* W_node    = (const float*)d_in[6];
    const float* b_node    = (const float*)d_in[7];

    float* out       = (float*)d_out;
    float* new_nodes = out;
    float* new_edges = out + (size_t)N_NODES * D_OUT;

    cudaFuncSetAttribute(gnn_kernel<true>,  cudaFuncAttributeMaxDynamicSharedMemorySize, SMEM_DYN);
    cudaFuncSetAttribute(gnn_kernel<false>, cudaFuncAttributeMaxDynamicSharedMemorySize, SMEM_DYN);

    const int GRID    = 3 * 148;            // 3 persistent CTAs per SM
    const int E_TILES = N_EDGES / BM;       // 25000
    const int E_HALF  = E_TILES / 2;        // 12500
    const int N_TILES = (N_NODES + BM - 1) / BM;   // 782

    prep_w_kernel<<<(2 * 12 * 8 * 32 + 255) / 256, 256>>>(W_edge, W_node);
    zero_received_kernel<<<592, 256>>>();

    // edge work split across two persistent launches (keeps ncu on an edge launch)
    gnn_kernel<true><<<GRID, 256, SMEM_DYN>>>(
        nodes, edges, senders, receivers, b_edge, new_edges, 0, E_HALF);
    gnn_kernel<true><<<GRID, 256, SMEM_DYN>>>(
        nodes, edges, senders, receivers, b_edge, new_edges, E_HALF, E_TILES - E_HALF);

    gnn_kernel<false><<<GRID, 256, SMEM_DYN>>>(
        nodes, nullptr, nullptr, nullptr, b_node, new_nodes, 0, N_TILES);
}